// round 16
// baseline (speedup 1.0000x reference)
#include <cuda_runtime.h>
#include <cuda_bf16.h>
#include <cstdint>
#include <cstddef>

#define B_   16
#define QT_  2048
#define KT_  2048
#define D_   1024
#define KSPLIT 16

// ---------------------------------------------------------------------------
// Scratch (device globals), ~0.96 GB
// ---------------------------------------------------------------------------
__device__ float         g_S [(size_t)B_ * QT_ * KT_];
__device__ __nv_bfloat16 g_Qh[(size_t)B_ * QT_ * D_];
__device__ __nv_bfloat16 g_Ql[(size_t)B_ * QT_ * D_];
__device__ __nv_bfloat16 g_Kh[(size_t)B_ * KT_ * D_];
__device__ __nv_bfloat16 g_Kl[(size_t)B_ * KT_ * D_];
__device__ __nv_bfloat16 g_Ph[(size_t)B_ * QT_ * KT_];
__device__ __nv_bfloat16 g_Pl[(size_t)B_ * QT_ * KT_];
__device__ __nv_bfloat16 g_Vh[(size_t)B_ * D_ * KT_];
__device__ __nv_bfloat16 g_Vl[(size_t)B_ * D_ * KT_];
__device__ float         g_Vp[(size_t)B_ * KSPLIT * D_];
__device__ float         g_Vm[(size_t)B_ * D_];

// ---------------------------------------------------------------------------
// Helpers
// ---------------------------------------------------------------------------
__device__ __forceinline__ uint32_t smem_u32(const void* p) {
    uint32_t a;
    asm("{ .reg .u64 t; cvta.to.shared.u64 t, %1; cvt.u32.u64 %0, t; }"
        : "=r"(a) : "l"(p));
    return a;
}
__device__ __forceinline__ void cpa16(uint32_t dst, const void* src) {
    asm volatile("cp.async.cg.shared.global [%0], [%1], 16;" :: "r"(dst), "l"(src));
}
#define CP_COMMIT() asm volatile("cp.async.commit_group;" ::: "memory")
#define CP_WAIT0()  asm volatile("cp.async.wait_group 0;" ::: "memory")
#define CP_WAIT1()  asm volatile("cp.async.wait_group 1;" ::: "memory")

__device__ __forceinline__ void lm4(uint32_t* r, uint32_t addr) {
    asm volatile("ldmatrix.sync.aligned.m8n8.x4.shared.b16 {%0,%1,%2,%3}, [%4];"
                 : "=r"(r[0]), "=r"(r[1]), "=r"(r[2]), "=r"(r[3]) : "r"(addr));
}
__device__ __forceinline__ void mma16816(float* c, const uint32_t* a,
                                         uint32_t b0, uint32_t b1) {
    asm volatile(
        "mma.sync.aligned.m16n8k16.row.col.f32.bf16.bf16.f32 "
        "{%0,%1,%2,%3}, {%4,%5,%6,%7}, {%8,%9}, {%0,%1,%2,%3};"
        : "+f"(c[0]), "+f"(c[1]), "+f"(c[2]), "+f"(c[3])
        : "r"(a[0]), "r"(a[1]), "r"(a[2]), "r"(a[3]), "r"(b0), "r"(b1));
}

// ---------------------------------------------------------------------------
// bf16 split GEMM, swizzled smem + 3-stage cp.async pipeline (proven core)
// ---------------------------------------------------------------------------
#define PART_BYTES 8192
#define BUF_BYTES  (4 * PART_BYTES)
#define NSTAGE 3

template <int MODE>
__global__ __launch_bounds__(256, 2)
void mma_gemm(const __nv_bfloat16* __restrict__ A0, const __nv_bfloat16* __restrict__ A1,
              const __nv_bfloat16* __restrict__ B0, const __nv_bfloat16* __restrict__ B1,
              float* __restrict__ C, int Kfull, int ldc,
              long strideA, long strideB, long strideC,
              const int* __restrict__ Qlen, const int* __restrict__ Klen,
              const float* __restrict__ Vmean)
{
    extern __shared__ char smem[];
    const uint32_t sb = smem_u32(smem);

    const int tid  = threadIdx.x;
    const int wid  = tid >> 5;
    const int lane = tid & 31;
    const int wm   = wid >> 2;
    const int wn   = wid & 3;
    const int bz   = blockIdx.z;
    const int n0   = blockIdx.x * 128;
    const int m0   = blockIdx.y * 128;

    const int ql = Qlen[bz];
    const int kl = Klen[bz];

    if (MODE == 1) {
        if (m0 >= ql || n0 >= kl) return;
    }

    const float* vm = (MODE == 2) ? (Vmean + (size_t)bz * D_) : nullptr;

    if (MODE == 2 && m0 >= ql) {
        const int r  = tid >> 1;
        const int c0 = (tid & 1) * 64;
        float* orow = C + (size_t)bz * strideC + (size_t)(m0 + r) * ldc + n0 + c0;
        const float* vsrc = vm + n0 + c0;
        #pragma unroll
        for (int j = 0; j < 16; ++j)
            ((float4*)orow)[j] = ((const float4*)vsrc)[j];
        return;
    }

    const __nv_bfloat16* Ap[2] = { A0 + (size_t)bz * strideA, A1 + (size_t)bz * strideA };
    const __nv_bfloat16* Bp[2] = { B0 + (size_t)bz * strideB, B1 + (size_t)bz * strideB };

    const int ld_row0 = tid >> 2;
    const int ld_ck   = tid & 3;
    const int ld_c    = ld_ck * 8;

    auto load_chunk = [&](int k0, int slot) {
        const uint32_t tb = sb + (uint32_t)slot * BUF_BYTES;
        #pragma unroll
        for (int p = 0; p < 2; ++p) {
            #pragma unroll
            for (int j = 0; j < 2; ++j) {
                const int r = ld_row0 + 64 * j;
                const uint32_t so =
                    (uint32_t)(r * 64 + ((ld_ck ^ ((r >> 1) & 3)) * 16));
                cpa16(tb + p * PART_BYTES + so,
                      Ap[p] + (size_t)(m0 + r) * Kfull + k0 + ld_c);
                cpa16(tb + (2 + p) * PART_BYTES + so,
                      Bp[p] + (size_t)(n0 + r) * Kfull + k0 + ld_c);
            }
        }
    };

    float acc[4][4][4];
    #pragma unroll
    for (int i = 0; i < 4; ++i)
        #pragma unroll
        for (int j = 0; j < 4; ++j)
            #pragma unroll
            for (int q = 0; q < 4; ++q) acc[i][j][q] = 0.f;

    int nchunks = Kfull / 32;
    if (MODE == 2) {
        const int nv = (kl + 31) >> 5;
        nchunks = nv < nchunks ? nv : nchunks;
    }

    load_chunk(0, 0);
    CP_COMMIT();
    if (nchunks > 1) { load_chunk(32, 1); CP_COMMIT(); }

    const int a_row = (lane & 15);
    const int a_hi  = (lane >> 4);
    const int b_row = (lane & 7) + ((lane >> 4) << 3);
    const int b_hi  = ((lane >> 3) & 1);

    for (int t = 0; t < nchunks; ++t) {
        if (t + 1 < nchunks) CP_WAIT1(); else CP_WAIT0();
        __syncthreads();
        if (t + 2 < nchunks) {
            load_chunk((t + 2) * 32, (t + 2) % NSTAGE);
            CP_COMMIT();
        }

        const uint32_t tb  = sb + (uint32_t)(t % NSTAGE) * BUF_BYTES;
        const uint32_t Ah_ = tb;
        const uint32_t Al_ = tb + PART_BYTES;
        const uint32_t Bh_ = tb + 2 * PART_BYTES;
        const uint32_t Bl_ = tb + 3 * PART_BYTES;

        #pragma unroll
        for (int kk = 0; kk < 2; ++kk) {
            uint32_t bh[2][4], bl[2][4], a[4][4];
            uint32_t aoff[4];
            #pragma unroll
            for (int np = 0; np < 2; ++np) {
                const int row = wn * 32 + np * 16 + b_row;
                const uint32_t boff =
                    (uint32_t)(row * 64 + (((kk * 2 + b_hi) ^ ((row >> 1) & 3)) * 16));
                lm4(bh[np], Bh_ + boff);
                lm4(bl[np], Bl_ + boff);
            }
            #pragma unroll
            for (int mt = 0; mt < 4; ++mt) {
                const int row = wm * 64 + mt * 16 + a_row;
                aoff[mt] =
                    (uint32_t)(row * 64 + (((kk * 2 + a_hi) ^ ((row >> 1) & 3)) * 16));
                lm4(a[mt], Ah_ + aoff[mt]);
            }
            #pragma unroll
            for (int mt = 0; mt < 4; ++mt)
                #pragma unroll
                for (int nf = 0; nf < 4; ++nf) {
                    mma16816(acc[mt][nf], a[mt], bh[nf >> 1][(nf & 1) * 2],
                                                 bh[nf >> 1][(nf & 1) * 2 + 1]);
                    mma16816(acc[mt][nf], a[mt], bl[nf >> 1][(nf & 1) * 2],
                                                 bl[nf >> 1][(nf & 1) * 2 + 1]);
                }
            #pragma unroll
            for (int mt = 0; mt < 4; ++mt)
                lm4(a[mt], Al_ + aoff[mt]);
            #pragma unroll
            for (int mt = 0; mt < 4; ++mt)
                #pragma unroll
                for (int nf = 0; nf < 4; ++nf)
                    mma16816(acc[mt][nf], a[mt], bh[nf >> 1][(nf & 1) * 2],
                                                 bh[nf >> 1][(nf & 1) * 2 + 1]);
        }
    }

    float* Cb = C + (size_t)bz * strideC;
    #pragma unroll
    for (int mt = 0; mt < 4; ++mt) {
        #pragma unroll
        for (int nf = 0; nf < 4; ++nf) {
            const int n = n0 + wn * 32 + nf * 8 + (lane & 3) * 2;
            float2 vmn;
            if (MODE == 2) vmn = *(const float2*)(vm + n);
            #pragma unroll
            for (int h = 0; h < 2; ++h) {
                const int m = m0 + wm * 64 + mt * 16 + (lane >> 2) + h * 8;
                float2 v = make_float2(acc[mt][nf][h * 2], acc[mt][nf][h * 2 + 1]);
                if (MODE == 2 && m >= ql) v = vmn;
                *(float2*)(Cb + (size_t)m * ldc + n) = v;
            }
        }
    }
}

// ---------------------------------------------------------------------------
// Merged length-aware split for Q and K: grid.y in [0,32), sel=y>>4, b=y&15
// ---------------------------------------------------------------------------
__global__ __launch_bounds__(256)
void split2_qk(const float* __restrict__ Q, const float* __restrict__ K,
               __nv_bfloat16* __restrict__ Qh, __nv_bfloat16* __restrict__ Ql,
               __nv_bfloat16* __restrict__ Kh, __nv_bfloat16* __restrict__ Kl,
               const int* __restrict__ Qlen, const int* __restrict__ Klen)
{
    const int y   = blockIdx.y;
    const int sel = y >> 4;
    const int b   = y & 15;
    const int row = blockIdx.x;
    const float* x = sel ? K : Q;
    __nv_bfloat16* h = sel ? Kh : Qh;
    __nv_bfloat16* l = sel ? Kl : Ql;
    const int len = sel ? Klen[b] : Qlen[b];
    if (row >= ((len + 127) & ~127)) return;
    const size_t i = ((size_t)b * QT_ + row) * (D_ / 4) + threadIdx.x;
    float4 v = ((const float4*)x)[i];
    float vv[4] = {v.x, v.y, v.z, v.w};
    __nv_bfloat16 hh[4], ll[4];
    #pragma unroll
    for (int j = 0; j < 4; ++j) {
        hh[j] = __float2bfloat16_rn(vv[j]);
        ll[j] = __float2bfloat16_rn(vv[j] - __bfloat162float(hh[j]));
    }
    ((__nv_bfloat162*)h)[2 * i + 0] = __nv_bfloat162(hh[0], hh[1]);
    ((__nv_bfloat162*)h)[2 * i + 1] = __nv_bfloat162(hh[2], hh[3]);
    ((__nv_bfloat162*)l)[2 * i + 0] = __nv_bfloat162(ll[0], ll[1]);
    ((__nv_bfloat162*)l)[2 * i + 1] = __nv_bfloat162(ll[2], ll[3]);
}

// ---------------------------------------------------------------------------
// V transpose + split (k-tiles beyond ceil32(kl) skipped)
// ---------------------------------------------------------------------------
__global__ __launch_bounds__(256)
void vt_split2(const float* __restrict__ V, __nv_bfloat16* __restrict__ Th,
               __nv_bfloat16* __restrict__ Tl, const int* __restrict__ Klen)
{
    const int bz = blockIdx.z;
    const int k0 = blockIdx.y * 32;
    if (k0 >= ((Klen[bz] + 31) & ~31)) return;
    __shared__ float tile[32][33];
    const int d0 = blockIdx.x * 32;
    const int tx = threadIdx.x, ty = threadIdx.y;
    const float* src = V + (size_t)bz * KT_ * D_;
    #pragma unroll
    for (int j = 0; j < 4; ++j)
        tile[ty + 8 * j][tx] = src[(size_t)(k0 + ty + 8 * j) * D_ + d0 + tx];
    __syncthreads();
    __nv_bfloat16* th = Th + (size_t)bz * D_ * KT_;
    __nv_bfloat16* tl = Tl + (size_t)bz * D_ * KT_;
    #pragma unroll
    for (int j = 0; j < 4; ++j) {
        const int d = d0 + ty + 8 * j;
        const float f = tile[tx][ty + 8 * j];
        const __nv_bfloat16 h = __float2bfloat16_rn(f);
        const __nv_bfloat16 l = __float2bfloat16_rn(f - __bfloat162float(h));
        th[(size_t)d * KT_ + k0 + tx] = h;
        tl[(size_t)d * KT_ + k0 + tx] = l;
    }
}

// ---------------------------------------------------------------------------
// vmean two-stage (over ALL KT rows)
// ---------------------------------------------------------------------------
__global__ __launch_bounds__(128)
void vmean_part(const float* __restrict__ V, float* __restrict__ P)
{
    const int b  = blockIdx.z;
    const int ks = blockIdx.y;
    const int d  = blockIdx.x * 128 + threadIdx.x;
    const float* src = V + (size_t)b * KT_ * D_ + (size_t)ks * (KT_ / KSPLIT) * D_ + d;
    float a0 = 0.f, a1 = 0.f, a2 = 0.f, a3 = 0.f;
    #pragma unroll 4
    for (int k = 0; k < KT_ / KSPLIT; k += 4) {
        a0 += src[(size_t)(k    ) * D_];
        a1 += src[(size_t)(k + 1) * D_];
        a2 += src[(size_t)(k + 2) * D_];
        a3 += src[(size_t)(k + 3) * D_];
    }
    P[((size_t)b * KSPLIT + ks) * D_ + d] = (a0 + a1) + (a2 + a3);
}

__global__ __launch_bounds__(256)
void vmean_red(const float* __restrict__ P, float* __restrict__ M)
{
    const int idx = blockIdx.x * 256 + threadIdx.x;
    const int b = idx / D_, d = idx % D_;
    const float* p = P + (size_t)b * KSPLIT * D_ + d;
    float s = 0.f;
    #pragma unroll
    for (int i = 0; i < KSPLIT; ++i) s += p[(size_t)i * D_];
    M[idx] = s * (1.0f / KT_);
}

// ---------------------------------------------------------------------------
// Length-aware softmax + split (slice form: pointers/lens pre-offset)
// ---------------------------------------------------------------------------
__global__ __launch_bounds__(256)
void softmax_split(const float* __restrict__ S, __nv_bfloat16* __restrict__ Ph,
                   __nv_bfloat16* __restrict__ Pl,
                   const int* __restrict__ Qlen, const int* __restrict__ Klen)
{
    const size_t row = blockIdx.x;
    const int b = (int)(row / QT_);
    const int q = (int)(row % QT_);
    const int ql = Qlen[b];
    const int kl = Klen[b];
    const int kend = (kl + 31) & ~31;
    const int tid = threadIdx.x, lane = tid & 31, wid = tid >> 5;
    const int base = tid * 8;

    if (q >= ((ql + 127) & ~127)) return;

    __nv_bfloat162* ph = (__nv_bfloat162*)(Ph + row * KT_);
    __nv_bfloat162* pl = (__nv_bfloat162*)(Pl + row * KT_);

    if (q >= ql) {
        if (base < kend) {
            const __nv_bfloat162 z = __float2bfloat162_rn(0.f);
            #pragma unroll
            for (int j = 0; j < 4; ++j) { ph[tid * 4 + j] = z; pl[tid * 4 + j] = z; }
        }
        return;
    }

    __shared__ float red[8];
    const float* srow = S + row * KT_;

    float x[8];
    if (base + 8 <= kl) {
        float4 a = ((const float4*)srow)[tid * 2];
        float4 c = ((const float4*)srow)[tid * 2 + 1];
        x[0] = a.x; x[1] = a.y; x[2] = a.z; x[3] = a.w;
        x[4] = c.x; x[5] = c.y; x[6] = c.z; x[7] = c.w;
    } else {
        #pragma unroll
        for (int j = 0; j < 8; ++j)
            x[j] = (base + j < kl) ? srow[base + j] : -1e30f;
    }

    float mx = fmaxf(fmaxf(fmaxf(x[0], x[1]), fmaxf(x[2], x[3])),
                     fmaxf(fmaxf(x[4], x[5]), fmaxf(x[6], x[7])));
    #pragma unroll
    for (int o = 16; o; o >>= 1) mx = fmaxf(mx, __shfl_xor_sync(~0u, mx, o));
    if (lane == 0) red[wid] = mx;
    __syncthreads();
    mx = red[0];
    #pragma unroll
    for (int i = 1; i < 8; ++i) mx = fmaxf(mx, red[i]);
    __syncthreads();

    float p[8];
    float s = 0.f;
    if (base < kl) {
        #pragma unroll
        for (int j = 0; j < 8; ++j) { p[j] = __expf(x[j] - mx); s += p[j]; }
    } else {
        #pragma unroll
        for (int j = 0; j < 8; ++j) p[j] = 0.f;
    }
    #pragma unroll
    for (int o = 16; o; o >>= 1) s += __shfl_xor_sync(~0u, s, o);
    if (lane == 0) red[wid] = s;
    __syncthreads();
    s = red[0];
    #pragma unroll
    for (int i = 1; i < 8; ++i) s += red[i];

    if (base >= kend) return;

    const float inv = 1.0f / s;
    __nv_bfloat16 hh[8], ll[8];
    #pragma unroll
    for (int j = 0; j < 8; ++j) {
        const float pv = p[j] * inv;
        hh[j] = __float2bfloat16_rn(pv);
        ll[j] = __float2bfloat16_rn(pv - __bfloat162float(hh[j]));
    }
    #pragma unroll
    for (int j = 0; j < 4; ++j) {
        ph[tid * 4 + j] = __nv_bfloat162(hh[2 * j], hh[2 * j + 1]);
        pl[tid * 4 + j] = __nv_bfloat162(ll[2 * j], ll[2 * j + 1]);
    }
}

// ---------------------------------------------------------------------------
// Launch (R9 schedule — empirically optimal across R7..R15):
//   M:  split_qk -> GEMM1(all) -> softmax(0-7) [evS0] -> softmax(8-15)
//       -> wait(evV) GEMM2(8-15) -> wait(evG2a)
//   s2: wait(evSplit) V-path [evV] -> wait(evS0) GEMM2(0-7) [evG2a]
// ---------------------------------------------------------------------------
extern "C" void kernel_launch(void* const* d_in, const int* in_sizes, int n_in,
                              void* d_out, int out_size)
{
    const float* Q    = (const float*)d_in[0];
    const float* K    = (const float*)d_in[1];
    const float* V    = (const float*)d_in[2];
    const int*   Qlen = (const int*)d_in[3];
    const int*   Klen = (const int*)d_in[4];
    float*       O    = (float*)d_out;

    float *S, *Vm, *Vp; __nv_bfloat16 *Qh, *Ql, *Kh, *Kl, *Ph, *Pl, *Vh, *Vl;
    cudaGetSymbolAddress((void**)&S,  g_S);
    cudaGetSymbolAddress((void**)&Vm, g_Vm);
    cudaGetSymbolAddress((void**)&Vp, g_Vp);
    cudaGetSymbolAddress((void**)&Qh, g_Qh); cudaGetSymbolAddress((void**)&Ql, g_Ql);
    cudaGetSymbolAddress((void**)&Kh, g_Kh); cudaGetSymbolAddress((void**)&Kl, g_Kl);
    cudaGetSymbolAddress((void**)&Ph, g_Ph); cudaGetSymbolAddress((void**)&Pl, g_Pl);
    cudaGetSymbolAddress((void**)&Vh, g_Vh); cudaGetSymbolAddress((void**)&Vl, g_Vl);

    static cudaStream_t s2 = nullptr;
    static cudaEvent_t evSplit = nullptr, evV = nullptr, evS0 = nullptr, evG2a = nullptr;
    if (s2 == nullptr) {
        cudaStreamCreateWithFlags(&s2, cudaStreamNonBlocking);
        cudaEventCreateWithFlags(&evSplit, cudaEventDisableTiming);
        cudaEventCreateWithFlags(&evV,     cudaEventDisableTiming);
        cudaEventCreateWithFlags(&evS0,    cudaEventDisableTiming);
        cudaEventCreateWithFlags(&evG2a,   cudaEventDisableTiming);
    }

    const int SMEM = NSTAGE * BUF_BYTES;   // 98304
    cudaFuncSetAttribute(mma_gemm<1>, cudaFuncAttributeMaxDynamicSharedMemorySize, SMEM);
    cudaFuncSetAttribute(mma_gemm<2>, cudaFuncAttributeMaxDynamicSharedMemorySize, SMEM);

    const int HB = B_ / 2;                   // 8 batches per half
    const size_t oS8  = (size_t)HB * QT_ * KT_;
    const size_t oVT8 = (size_t)HB * D_ * KT_;
    const size_t oQ8  = (size_t)HB * QT_ * D_;

    // main: split Q/K
    split2_qk<<<dim3(QT_, 32), 256>>>(Q, K, Qh, Ql, Kh, Kl, Qlen, Klen);
    cudaEventRecord(evSplit, 0);

    // s2: V-path, concurrent with GEMM1 on main
    cudaStreamWaitEvent(s2, evSplit, 0);
    vt_split2<<<dim3(D_ / 32, KT_ / 32, B_), dim3(32, 8), 0, s2>>>(V, Vh, Vl, Klen);
    vmean_part<<<dim3(D_ / 128, KSPLIT, B_), 128, 0, s2>>>(V, Vp);
    vmean_red<<<(B_ * D_) / 256, 256, 0, s2>>>(Vp, Vm);
    cudaEventRecord(evV, s2);

    // main: GEMM1 (all batches)
    mma_gemm<1><<<dim3(KT_ / 128, QT_ / 128, B_), 256, SMEM>>>(
        Qh, Ql, Kh, Kl, S, D_, KT_,
        (long)QT_ * D_, (long)KT_ * D_, (long)QT_ * KT_, Qlen, Klen, nullptr);

    // main: softmax first half, then second half
    softmax_split<<<HB * QT_, 256>>>(S, Ph, Pl, Qlen, Klen);
    cudaEventRecord(evS0, 0);
    softmax_split<<<HB * QT_, 256>>>(S + oS8, Ph + oS8, Pl + oS8, Qlen + HB, Klen + HB);

    // s2: GEMM2 first half (needs V-path done [in-stream] + softmax first half)
    cudaStreamWaitEvent(s2, evS0, 0);
    mma_gemm<2><<<dim3(D_ / 128, QT_ / 128, HB), 256, SMEM, s2>>>(
        Ph, Pl, Vh, Vl, O, KT_, D_,
        (long)QT_ * KT_, (long)D_ * KT_, (long)QT_ * D_, Qlen, Klen, Vm);
    cudaEventRecord(evG2a, s2);

    // main: GEMM2 second half (needs V-path done)
    cudaStreamWaitEvent(0, evV, 0);
    mma_gemm<2><<<dim3(D_ / 128, QT_ / 128, HB), 256, SMEM>>>(
        Ph + oS8, Pl + oS8, Vh + oVT8, Vl + oVT8, O + oQ8, KT_, D_,
        (long)QT_ * KT_, (long)D_ * KT_, (long)QT_ * D_,
        Qlen + HB, Klen + HB, Vm + (size_t)HB * D_);

    // join
    cudaStreamWaitEvent(0, evG2a, 0);
}

// round 17
// speedup vs baseline: 1.5033x; 1.5033x over previous
#include <cuda_runtime.h>
#include <cuda_bf16.h>
#include <cstdint>
#include <cstddef>

#define B_   16
#define QT_  2048
#define KT_  2048
#define D_   1024
#define KSPLIT 16

// ---------------------------------------------------------------------------
// Scratch (device globals), ~0.96 GB
// ---------------------------------------------------------------------------
__device__ float         g_S [(size_t)B_ * QT_ * KT_];
__device__ __nv_bfloat16 g_Qh[(size_t)B_ * QT_ * D_];
__device__ __nv_bfloat16 g_Ql[(size_t)B_ * QT_ * D_];
__device__ __nv_bfloat16 g_Kh[(size_t)B_ * KT_ * D_];
__device__ __nv_bfloat16 g_Kl[(size_t)B_ * KT_ * D_];
__device__ __nv_bfloat16 g_Ph[(size_t)B_ * QT_ * KT_];
__device__ __nv_bfloat16 g_Pl[(size_t)B_ * QT_ * KT_];
__device__ __nv_bfloat16 g_Vh[(size_t)B_ * D_ * KT_];
__device__ __nv_bfloat16 g_Vl[(size_t)B_ * D_ * KT_];
__device__ float         g_Vp[(size_t)B_ * KSPLIT * D_];
__device__ float         g_Vm[(size_t)B_ * D_];

// ---------------------------------------------------------------------------
// Helpers
// ---------------------------------------------------------------------------
__device__ __forceinline__ uint32_t smem_u32(const void* p) {
    uint32_t a;
    asm("{ .reg .u64 t; cvta.to.shared.u64 t, %1; cvt.u32.u64 %0, t; }"
        : "=r"(a) : "l"(p));
    return a;
}
__device__ __forceinline__ void cpa16(uint32_t dst, const void* src) {
    asm volatile("cp.async.cg.shared.global [%0], [%1], 16;" :: "r"(dst), "l"(src));
}
#define CP_COMMIT() asm volatile("cp.async.commit_group;" ::: "memory")
#define CP_WAIT0()  asm volatile("cp.async.wait_group 0;" ::: "memory")
#define CP_WAIT1()  asm volatile("cp.async.wait_group 1;" ::: "memory")

__device__ __forceinline__ void lm4(uint32_t* r, uint32_t addr) {
    asm volatile("ldmatrix.sync.aligned.m8n8.x4.shared.b16 {%0,%1,%2,%3}, [%4];"
                 : "=r"(r[0]), "=r"(r[1]), "=r"(r[2]), "=r"(r[3]) : "r"(addr));
}
__device__ __forceinline__ void mma16816(float* c, const uint32_t* a,
                                         uint32_t b0, uint32_t b1) {
    asm volatile(
        "mma.sync.aligned.m16n8k16.row.col.f32.bf16.bf16.f32 "
        "{%0,%1,%2,%3}, {%4,%5,%6,%7}, {%8,%9}, {%0,%1,%2,%3};"
        : "+f"(c[0]), "+f"(c[1]), "+f"(c[2]), "+f"(c[3])
        : "r"(a[0]), "r"(a[1]), "r"(a[2]), "r"(a[3]), "r"(b0), "r"(b1));
}

// ---------------------------------------------------------------------------
// bf16 split GEMM, swizzled smem + 3-stage cp.async pipeline (proven core)
// ---------------------------------------------------------------------------
#define PART_BYTES 8192
#define BUF_BYTES  (4 * PART_BYTES)
#define NSTAGE 3

template <int MODE>
__global__ __launch_bounds__(256, 2)
void mma_gemm(const __nv_bfloat16* __restrict__ A0, const __nv_bfloat16* __restrict__ A1,
              const __nv_bfloat16* __restrict__ B0, const __nv_bfloat16* __restrict__ B1,
              float* __restrict__ C, int Kfull, int ldc,
              long strideA, long strideB, long strideC,
              const int* __restrict__ Qlen, const int* __restrict__ Klen,
              const float* __restrict__ Vmean)
{
    extern __shared__ char smem[];
    const uint32_t sb = smem_u32(smem);

    const int tid  = threadIdx.x;
    const int wid  = tid >> 5;
    const int lane = tid & 31;
    const int wm   = wid >> 2;
    const int wn   = wid & 3;
    const int bz   = blockIdx.z;
    const int n0   = blockIdx.x * 128;
    const int m0   = blockIdx.y * 128;

    const int ql = Qlen[bz];
    const int kl = Klen[bz];

    if (MODE == 1) {
        if (m0 >= ql || n0 >= kl) return;
    }

    const float* vm = (MODE == 2) ? (Vmean + (size_t)bz * D_) : nullptr;

    if (MODE == 2 && m0 >= ql) {
        const int r  = tid >> 1;
        const int c0 = (tid & 1) * 64;
        float* orow = C + (size_t)bz * strideC + (size_t)(m0 + r) * ldc + n0 + c0;
        const float* vsrc = vm + n0 + c0;
        #pragma unroll
        for (int j = 0; j < 16; ++j)
            ((float4*)orow)[j] = ((const float4*)vsrc)[j];
        return;
    }

    const __nv_bfloat16* Ap[2] = { A0 + (size_t)bz * strideA, A1 + (size_t)bz * strideA };
    const __nv_bfloat16* Bp[2] = { B0 + (size_t)bz * strideB, B1 + (size_t)bz * strideB };

    const int ld_row0 = tid >> 2;
    const int ld_ck   = tid & 3;
    const int ld_c    = ld_ck * 8;

    auto load_chunk = [&](int k0, int slot) {
        const uint32_t tb = sb + (uint32_t)slot * BUF_BYTES;
        #pragma unroll
        for (int p = 0; p < 2; ++p) {
            #pragma unroll
            for (int j = 0; j < 2; ++j) {
                const int r = ld_row0 + 64 * j;
                const uint32_t so =
                    (uint32_t)(r * 64 + ((ld_ck ^ ((r >> 1) & 3)) * 16));
                cpa16(tb + p * PART_BYTES + so,
                      Ap[p] + (size_t)(m0 + r) * Kfull + k0 + ld_c);
                cpa16(tb + (2 + p) * PART_BYTES + so,
                      Bp[p] + (size_t)(n0 + r) * Kfull + k0 + ld_c);
            }
        }
    };

    float acc[4][4][4];
    #pragma unroll
    for (int i = 0; i < 4; ++i)
        #pragma unroll
        for (int j = 0; j < 4; ++j)
            #pragma unroll
            for (int q = 0; q < 4; ++q) acc[i][j][q] = 0.f;

    int nchunks = Kfull / 32;
    if (MODE == 2) {
        const int nv = (kl + 31) >> 5;
        nchunks = nv < nchunks ? nv : nchunks;
    }

    load_chunk(0, 0);
    CP_COMMIT();
    if (nchunks > 1) { load_chunk(32, 1); CP_COMMIT(); }

    const int a_row = (lane & 15);
    const int a_hi  = (lane >> 4);
    const int b_row = (lane & 7) + ((lane >> 4) << 3);
    const int b_hi  = ((lane >> 3) & 1);

    for (int t = 0; t < nchunks; ++t) {
        if (t + 1 < nchunks) CP_WAIT1(); else CP_WAIT0();
        __syncthreads();
        if (t + 2 < nchunks) {
            load_chunk((t + 2) * 32, (t + 2) % NSTAGE);
            CP_COMMIT();
        }

        const uint32_t tb  = sb + (uint32_t)(t % NSTAGE) * BUF_BYTES;
        const uint32_t Ah_ = tb;
        const uint32_t Al_ = tb + PART_BYTES;
        const uint32_t Bh_ = tb + 2 * PART_BYTES;
        const uint32_t Bl_ = tb + 3 * PART_BYTES;

        #pragma unroll
        for (int kk = 0; kk < 2; ++kk) {
            uint32_t bh[2][4], bl[2][4], a[4][4];
            uint32_t aoff[4];
            #pragma unroll
            for (int np = 0; np < 2; ++np) {
                const int row = wn * 32 + np * 16 + b_row;
                const uint32_t boff =
                    (uint32_t)(row * 64 + (((kk * 2 + b_hi) ^ ((row >> 1) & 3)) * 16));
                lm4(bh[np], Bh_ + boff);
                lm4(bl[np], Bl_ + boff);
            }
            #pragma unroll
            for (int mt = 0; mt < 4; ++mt) {
                const int row = wm * 64 + mt * 16 + a_row;
                aoff[mt] =
                    (uint32_t)(row * 64 + (((kk * 2 + a_hi) ^ ((row >> 1) & 3)) * 16));
                lm4(a[mt], Ah_ + aoff[mt]);
            }
            #pragma unroll
            for (int mt = 0; mt < 4; ++mt)
                #pragma unroll
                for (int nf = 0; nf < 4; ++nf) {
                    mma16816(acc[mt][nf], a[mt], bh[nf >> 1][(nf & 1) * 2],
                                                 bh[nf >> 1][(nf & 1) * 2 + 1]);
                    mma16816(acc[mt][nf], a[mt], bl[nf >> 1][(nf & 1) * 2],
                                                 bl[nf >> 1][(nf & 1) * 2 + 1]);
                }
            #pragma unroll
            for (int mt = 0; mt < 4; ++mt)
                lm4(a[mt], Al_ + aoff[mt]);
            #pragma unroll
            for (int mt = 0; mt < 4; ++mt)
                #pragma unroll
                for (int nf = 0; nf < 4; ++nf)
                    mma16816(acc[mt][nf], a[mt], bh[nf >> 1][(nf & 1) * 2],
                                                 bh[nf >> 1][(nf & 1) * 2 + 1]);
        }
    }

    float* Cb = C + (size_t)bz * strideC;
    #pragma unroll
    for (int mt = 0; mt < 4; ++mt) {
        #pragma unroll
        for (int nf = 0; nf < 4; ++nf) {
            const int n = n0 + wn * 32 + nf * 8 + (lane & 3) * 2;
            float2 vmn;
            if (MODE == 2) vmn = *(const float2*)(vm + n);
            #pragma unroll
            for (int h = 0; h < 2; ++h) {
                const int m = m0 + wm * 64 + mt * 16 + (lane >> 2) + h * 8;
                float2 v = make_float2(acc[mt][nf][h * 2], acc[mt][nf][h * 2 + 1]);
                if (MODE == 2 && m >= ql) v = vmn;
                *(float2*)(Cb + (size_t)m * ldc + n) = v;
            }
        }
    }
}

// ---------------------------------------------------------------------------
// Merged length-aware split for Q and K: grid.y in [0,32), sel=y>>4, b=y&15
// ---------------------------------------------------------------------------
__global__ __launch_bounds__(256)
void split2_qk(const float* __restrict__ Q, const float* __restrict__ K,
               __nv_bfloat16* __restrict__ Qh, __nv_bfloat16* __restrict__ Ql,
               __nv_bfloat16* __restrict__ Kh, __nv_bfloat16* __restrict__ Kl,
               const int* __restrict__ Qlen, const int* __restrict__ Klen)
{
    const int y   = blockIdx.y;
    const int sel = y >> 4;
    const int b   = y & 15;
    const int row = blockIdx.x;
    const float* x = sel ? K : Q;
    __nv_bfloat16* h = sel ? Kh : Qh;
    __nv_bfloat16* l = sel ? Kl : Ql;
    const int len = sel ? Klen[b] : Qlen[b];
    if (row >= ((len + 127) & ~127)) return;
    const size_t i = ((size_t)b * QT_ + row) * (D_ / 4) + threadIdx.x;
    float4 v = ((const float4*)x)[i];
    float vv[4] = {v.x, v.y, v.z, v.w};
    __nv_bfloat16 hh[4], ll[4];
    #pragma unroll
    for (int j = 0; j < 4; ++j) {
        hh[j] = __float2bfloat16_rn(vv[j]);
        ll[j] = __float2bfloat16_rn(vv[j] - __bfloat162float(hh[j]));
    }
    ((__nv_bfloat162*)h)[2 * i + 0] = __nv_bfloat162(hh[0], hh[1]);
    ((__nv_bfloat162*)h)[2 * i + 1] = __nv_bfloat162(hh[2], hh[3]);
    ((__nv_bfloat162*)l)[2 * i + 0] = __nv_bfloat162(ll[0], ll[1]);
    ((__nv_bfloat162*)l)[2 * i + 1] = __nv_bfloat162(ll[2], ll[3]);
}

// ---------------------------------------------------------------------------
// V transpose + split (k-tiles beyond ceil32(kl) skipped)
// ---------------------------------------------------------------------------
__global__ __launch_bounds__(256)
void vt_split2(const float* __restrict__ V, __nv_bfloat16* __restrict__ Th,
               __nv_bfloat16* __restrict__ Tl, const int* __restrict__ Klen)
{
    const int bz = blockIdx.z;
    const int k0 = blockIdx.y * 32;
    if (k0 >= ((Klen[bz] + 31) & ~31)) return;
    __shared__ float tile[32][33];
    const int d0 = blockIdx.x * 32;
    const int tx = threadIdx.x, ty = threadIdx.y;
    const float* src = V + (size_t)bz * KT_ * D_;
    #pragma unroll
    for (int j = 0; j < 4; ++j)
        tile[ty + 8 * j][tx] = src[(size_t)(k0 + ty + 8 * j) * D_ + d0 + tx];
    __syncthreads();
    __nv_bfloat16* th = Th + (size_t)bz * D_ * KT_;
    __nv_bfloat16* tl = Tl + (size_t)bz * D_ * KT_;
    #pragma unroll
    for (int j = 0; j < 4; ++j) {
        const int d = d0 + ty + 8 * j;
        const float f = tile[tx][ty + 8 * j];
        const __nv_bfloat16 h = __float2bfloat16_rn(f);
        const __nv_bfloat16 l = __float2bfloat16_rn(f - __bfloat162float(h));
        th[(size_t)d * KT_ + k0 + tx] = h;
        tl[(size_t)d * KT_ + k0 + tx] = l;
    }
}

// ---------------------------------------------------------------------------
// vmean two-stage (over ALL KT rows)
// ---------------------------------------------------------------------------
__global__ __launch_bounds__(128)
void vmean_part(const float* __restrict__ V, float* __restrict__ P)
{
    const int b  = blockIdx.z;
    const int ks = blockIdx.y;
    const int d  = blockIdx.x * 128 + threadIdx.x;
    const float* src = V + (size_t)b * KT_ * D_ + (size_t)ks * (KT_ / KSPLIT) * D_ + d;
    float a0 = 0.f, a1 = 0.f, a2 = 0.f, a3 = 0.f;
    #pragma unroll 4
    for (int k = 0; k < KT_ / KSPLIT; k += 4) {
        a0 += src[(size_t)(k    ) * D_];
        a1 += src[(size_t)(k + 1) * D_];
        a2 += src[(size_t)(k + 2) * D_];
        a3 += src[(size_t)(k + 3) * D_];
    }
    P[((size_t)b * KSPLIT + ks) * D_ + d] = (a0 + a1) + (a2 + a3);
}

__global__ __launch_bounds__(256)
void vmean_red(const float* __restrict__ P, float* __restrict__ M)
{
    const int idx = blockIdx.x * 256 + threadIdx.x;
    const int b = idx / D_, d = idx % D_;
    const float* p = P + (size_t)b * KSPLIT * D_ + d;
    float s = 0.f;
    #pragma unroll
    for (int i = 0; i < KSPLIT; ++i) s += p[(size_t)i * D_];
    M[idx] = s * (1.0f / KT_);
}

// ---------------------------------------------------------------------------
// Length-aware softmax + split (slice form: pointers/lens pre-offset)
// ---------------------------------------------------------------------------
__global__ __launch_bounds__(256)
void softmax_split(const float* __restrict__ S, __nv_bfloat16* __restrict__ Ph,
                   __nv_bfloat16* __restrict__ Pl,
                   const int* __restrict__ Qlen, const int* __restrict__ Klen)
{
    const size_t row = blockIdx.x;
    const int b = (int)(row / QT_);
    const int q = (int)(row % QT_);
    const int ql = Qlen[b];
    const int kl = Klen[b];
    const int kend = (kl + 31) & ~31;
    const int tid = threadIdx.x, lane = tid & 31, wid = tid >> 5;
    const int base = tid * 8;

    if (q >= ((ql + 127) & ~127)) return;

    __nv_bfloat162* ph = (__nv_bfloat162*)(Ph + row * KT_);
    __nv_bfloat162* pl = (__nv_bfloat162*)(Pl + row * KT_);

    if (q >= ql) {
        if (base < kend) {
            const __nv_bfloat162 z = __float2bfloat162_rn(0.f);
            #pragma unroll
            for (int j = 0; j < 4; ++j) { ph[tid * 4 + j] = z; pl[tid * 4 + j] = z; }
        }
        return;
    }

    __shared__ float red[8];
    const float* srow = S + row * KT_;

    float x[8];
    if (base + 8 <= kl) {
        float4 a = ((const float4*)srow)[tid * 2];
        float4 c = ((const float4*)srow)[tid * 2 + 1];
        x[0] = a.x; x[1] = a.y; x[2] = a.z; x[3] = a.w;
        x[4] = c.x; x[5] = c.y; x[6] = c.z; x[7] = c.w;
    } else {
        #pragma unroll
        for (int j = 0; j < 8; ++j)
            x[j] = (base + j < kl) ? srow[base + j] : -1e30f;
    }

    float mx = fmaxf(fmaxf(fmaxf(x[0], x[1]), fmaxf(x[2], x[3])),
                     fmaxf(fmaxf(x[4], x[5]), fmaxf(x[6], x[7])));
    #pragma unroll
    for (int o = 16; o; o >>= 1) mx = fmaxf(mx, __shfl_xor_sync(~0u, mx, o));
    if (lane == 0) red[wid] = mx;
    __syncthreads();
    mx = red[0];
    #pragma unroll
    for (int i = 1; i < 8; ++i) mx = fmaxf(mx, red[i]);
    __syncthreads();

    float p[8];
    float s = 0.f;
    if (base < kl) {
        #pragma unroll
        for (int j = 0; j < 8; ++j) { p[j] = __expf(x[j] - mx); s += p[j]; }
    } else {
        #pragma unroll
        for (int j = 0; j < 8; ++j) p[j] = 0.f;
    }
    #pragma unroll
    for (int o = 16; o; o >>= 1) s += __shfl_xor_sync(~0u, s, o);
    if (lane == 0) red[wid] = s;
    __syncthreads();
    s = red[0];
    #pragma unroll
    for (int i = 1; i < 8; ++i) s += red[i];

    if (base >= kend) return;

    const float inv = 1.0f / s;
    __nv_bfloat16 hh[8], ll[8];
    #pragma unroll
    for (int j = 0; j < 8; ++j) {
        const float pv = p[j] * inv;
        hh[j] = __float2bfloat16_rn(pv);
        ll[j] = __float2bfloat16_rn(pv - __bfloat162float(hh[j]));
    }
    #pragma unroll
    for (int j = 0; j < 4; ++j) {
        ph[tid * 4 + j] = __nv_bfloat162(hh[2 * j], hh[2 * j + 1]);
        pl[tid * 4 + j] = __nv_bfloat162(ll[2 * j], ll[2 * j + 1]);
    }
}

// ---------------------------------------------------------------------------
// Launch (R9 schedule — empirically optimal; resubmitted unchanged after the
// R16 977us outlier, which was environment noise on a byte-identical binary):
//   M:  split_qk -> GEMM1(all) -> softmax(0-7) [evS0] -> softmax(8-15)
//       -> wait(evV) GEMM2(8-15) -> wait(evG2a)
//   s2: wait(evSplit) V-path [evV] -> wait(evS0) GEMM2(0-7) [evG2a]
// ---------------------------------------------------------------------------
extern "C" void kernel_launch(void* const* d_in, const int* in_sizes, int n_in,
                              void* d_out, int out_size)
{
    const float* Q    = (const float*)d_in[0];
    const float* K    = (const float*)d_in[1];
    const float* V    = (const float*)d_in[2];
    const int*   Qlen = (const int*)d_in[3];
    const int*   Klen = (const int*)d_in[4];
    float*       O    = (float*)d_out;

    float *S, *Vm, *Vp; __nv_bfloat16 *Qh, *Ql, *Kh, *Kl, *Ph, *Pl, *Vh, *Vl;
    cudaGetSymbolAddress((void**)&S,  g_S);
    cudaGetSymbolAddress((void**)&Vm, g_Vm);
    cudaGetSymbolAddress((void**)&Vp, g_Vp);
    cudaGetSymbolAddress((void**)&Qh, g_Qh); cudaGetSymbolAddress((void**)&Ql, g_Ql);
    cudaGetSymbolAddress((void**)&Kh, g_Kh); cudaGetSymbolAddress((void**)&Kl, g_Kl);
    cudaGetSymbolAddress((void**)&Ph, g_Ph); cudaGetSymbolAddress((void**)&Pl, g_Pl);
    cudaGetSymbolAddress((void**)&Vh, g_Vh); cudaGetSymbolAddress((void**)&Vl, g_Vl);

    static cudaStream_t s2 = nullptr;
    static cudaEvent_t evSplit = nullptr, evV = nullptr, evS0 = nullptr, evG2a = nullptr;
    if (s2 == nullptr) {
        cudaStreamCreateWithFlags(&s2, cudaStreamNonBlocking);
        cudaEventCreateWithFlags(&evSplit, cudaEventDisableTiming);
        cudaEventCreateWithFlags(&evV,     cudaEventDisableTiming);
        cudaEventCreateWithFlags(&evS0,    cudaEventDisableTiming);
        cudaEventCreateWithFlags(&evG2a,   cudaEventDisableTiming);
    }

    const int SMEM = NSTAGE * BUF_BYTES;   // 98304
    cudaFuncSetAttribute(mma_gemm<1>, cudaFuncAttributeMaxDynamicSharedMemorySize, SMEM);
    cudaFuncSetAttribute(mma_gemm<2>, cudaFuncAttributeMaxDynamicSharedMemorySize, SMEM);

    const int HB = B_ / 2;                   // 8 batches per half
    const size_t oS8  = (size_t)HB * QT_ * KT_;
    const size_t oVT8 = (size_t)HB * D_ * KT_;
    const size_t oQ8  = (size_t)HB * QT_ * D_;

    // main: split Q/K
    split2_qk<<<dim3(QT_, 32), 256>>>(Q, K, Qh, Ql, Kh, Kl, Qlen, Klen);
    cudaEventRecord(evSplit, 0);

    // s2: V-path, concurrent with GEMM1 on main
    cudaStreamWaitEvent(s2, evSplit, 0);
    vt_split2<<<dim3(D_ / 32, KT_ / 32, B_), dim3(32, 8), 0, s2>>>(V, Vh, Vl, Klen);
    vmean_part<<<dim3(D_ / 128, KSPLIT, B_), 128, 0, s2>>>(V, Vp);
    vmean_red<<<(B_ * D_) / 256, 256, 0, s2>>>(Vp, Vm);
    cudaEventRecord(evV, s2);

    // main: GEMM1 (all batches)
    mma_gemm<1><<<dim3(KT_ / 128, QT_ / 128, B_), 256, SMEM>>>(
        Qh, Ql, Kh, Kl, S, D_, KT_,
        (long)QT_ * D_, (long)KT_ * D_, (long)QT_ * KT_, Qlen, Klen, nullptr);

    // main: softmax first half, then second half
    softmax_split<<<HB * QT_, 256>>>(S, Ph, Pl, Qlen, Klen);
    cudaEventRecord(evS0, 0);
    softmax_split<<<HB * QT_, 256>>>(S + oS8, Ph + oS8, Pl + oS8, Qlen + HB, Klen + HB);

    // s2: GEMM2 first half (needs V-path done [in-stream] + softmax first half)
    cudaStreamWaitEvent(s2, evS0, 0);
    mma_gemm<2><<<dim3(D_ / 128, QT_ / 128, HB), 256, SMEM, s2>>>(
        Ph, Pl, Vh, Vl, O, KT_, D_,
        (long)QT_ * KT_, (long)D_ * KT_, (long)QT_ * D_, Qlen, Klen, Vm);
    cudaEventRecord(evG2a, s2);

    // main: GEMM2 second half (needs V-path done)
    cudaStreamWaitEvent(0, evV, 0);
    mma_gemm<2><<<dim3(D_ / 128, QT_ / 128, HB), 256, SMEM>>>(
        Ph + oS8, Pl + oS8, Vh + oVT8, Vl + oVT8, O + oQ8, KT_, D_,
        (long)QT_ * KT_, (long)D_ * KT_, (long)QT_ * D_,
        Qlen + HB, Klen + HB, Vm + (size_t)HB * D_);

    // join
    cudaStreamWaitEvent(0, evG2a, 0);
}